// round 1
// baseline (speedup 1.0000x reference)
#include <cuda_runtime.h>
#include <cstdint>

#define D 128

// Scratch: transposed weight matrix Wt[k][n] = W[n][k] (64 KB, static device mem)
__device__ float g_Wt[D * D];

// ---------------------------------------------------------------------------
// Kernel 0: transpose W (128x128) into g_Wt. Writes coalesced, reads strided
// (tiny: 16384 elements, sub-microsecond).
// ---------------------------------------------------------------------------
__global__ void k_transpose(const float* __restrict__ W) {
    int idx = blockIdx.x * blockDim.x + threadIdx.x;
    if (idx < D * D) {
        int k = idx / D, n = idx % D;
        g_Wt[idx] = W[n * D + k];
    }
}

// ---------------------------------------------------------------------------
// Kernel 1: zero the accumulator (which lives in d_out). float4 stores.
// ---------------------------------------------------------------------------
__global__ void k_zero(float4* __restrict__ out, int n4) {
    int i = blockIdx.x * blockDim.x + threadIdx.x;
    int stride = gridDim.x * blockDim.x;
    float4 z = make_float4(0.f, 0.f, 0.f, 0.f);
    for (; i < n4; i += stride) out[i] = z;
}

// ---------------------------------------------------------------------------
// Kernel 2: edge scatter-sum. acc[dst] += h[src], 128 floats per edge.
// One warp per 32 edges: edge indices loaded coalesced (one per lane), then
// broadcast via shfl; each lane owns 4 contiguous floats of the feature row
// (float4 load from L2-resident h, one vector reduction to L2-resident acc).
// red.global.add.v4.f32 (sm_90+) keeps the atomic count at 1 op / 16 B.
// ---------------------------------------------------------------------------
__device__ __forceinline__ void red_add_v4(float* addr, float4 v) {
    asm volatile("red.global.add.v4.f32 [%0], {%1,%2,%3,%4};"
                 :: "l"(addr), "f"(v.x), "f"(v.y), "f"(v.z), "f"(v.w)
                 : "memory");
}

__global__ void k_scatter(const float* __restrict__ h,
                          const int* __restrict__ src,
                          const int* __restrict__ dst,
                          float* __restrict__ acc, int E) {
    int warp = (blockIdx.x * blockDim.x + threadIdx.x) >> 5;
    int lane = threadIdx.x & 31;
    int base = warp * 32;
    if (base >= E) return;

    int e = base + lane;
    int s = 0, d = 0;
    if (e < E) { s = src[e]; d = dst[e]; }
    int cnt = min(32, E - base);

    for (int i = 0; i < cnt; i++) {
        int si = __shfl_sync(0xffffffffu, s, i);
        int di = __shfl_sync(0xffffffffu, d, i);
        float4 v = *(const float4*)(h + (size_t)si * D + lane * 4);
        red_add_v4(acc + (size_t)di * D + lane * 4, v);
    }
}

// ---------------------------------------------------------------------------
// Kernel 3: out = relu(acc @ W^T + b), IN PLACE (acc == out).
// Safe because each block only reads its own 64 output rows and stores strictly
// after the k-loop. Full Wt (64 KB) staged in smem once per block; b_frag
// float4 LDS is conflict-free (consecutive n), A-tile LDS is warp-uniform
// broadcast. Each thread computes an 8x4 microtile -> FFMA-issue-bound.
// ---------------------------------------------------------------------------
#define GM_BM 64
#define GM_BK 16
#define GM_SMEM_BYTES ((D * D + GM_BM * GM_BK) * 4)  // 69632

__global__ void k_gemm(const float* __restrict__ A,     // [M,128] (== out)
                       const float* __restrict__ bias,  // [128]
                       float* __restrict__ out, int M) {
    extern __shared__ float sm[];
    float* Ws = sm;            // [128][128] = Wt (k-major)
    float* As = sm + D * D;    // [64][16]

    int tid = threadIdx.x;     // 256 threads
    // Stage Wt into smem (coalesced float4, 16 iters)
    for (int i = tid * 4; i < D * D; i += 256 * 4)
        *(float4*)(Ws + i) = *(const float4*)(g_Wt + i);

    int m0 = blockIdx.x * GM_BM;
    int tx = tid & 31;   // n-group: columns tx*4 .. tx*4+3
    int ty = tid >> 5;   // row-group: rows ty*8 .. ty*8+7

    float acc[8][4];
#pragma unroll
    for (int i = 0; i < 8; i++)
#pragma unroll
        for (int j = 0; j < 4; j++) acc[i][j] = 0.f;

    int lr = tid >> 2;          // A-tile load row (0..63)
    int lc = (tid & 3) * 4;     // A-tile load col (0,4,8,12)

    __syncthreads();

    for (int k0 = 0; k0 < D; k0 += GM_BK) {
        int gm = m0 + lr;
        float4 av = make_float4(0.f, 0.f, 0.f, 0.f);
        if (gm < M) av = *(const float4*)(A + (size_t)gm * D + k0 + lc);
        __syncthreads();
        *(float4*)(As + lr * GM_BK + lc) = av;
        __syncthreads();

#pragma unroll
        for (int kk = 0; kk < GM_BK; kk++) {
            float4 bv = *(float4*)(Ws + (k0 + kk) * D + tx * 4);
#pragma unroll
            for (int i = 0; i < 8; i++) {
                float a = As[(ty * 8 + i) * GM_BK + kk];
                acc[i][0] += a * bv.x;
                acc[i][1] += a * bv.y;
                acc[i][2] += a * bv.z;
                acc[i][3] += a * bv.w;
            }
        }
    }

    float4 bb = *(const float4*)(bias + tx * 4);
#pragma unroll
    for (int i = 0; i < 8; i++) {
        int gm = m0 + ty * 8 + i;
        if (gm < M) {
            float4 o;
            o.x = fmaxf(acc[i][0] + bb.x, 0.f);
            o.y = fmaxf(acc[i][1] + bb.y, 0.f);
            o.z = fmaxf(acc[i][2] + bb.z, 0.f);
            o.w = fmaxf(acc[i][3] + bb.w, 0.f);
            *(float4*)(out + (size_t)gm * D + tx * 4) = o;
        }
    }
}

// ---------------------------------------------------------------------------
// Launch: transpose -> zero -> scatter -> gemm (stream-ordered, capturable).
// ---------------------------------------------------------------------------
extern "C" void kernel_launch(void* const* d_in, const int* in_sizes, int n_in,
                              void* d_out, int out_size) {
    const float* h    = (const float*)d_in[0];
    const int*   esrc = (const int*)d_in[1];
    const int*   edst = (const int*)d_in[2];
    const float* W    = (const float*)d_in[3];
    const float* b    = (const float*)d_in[4];
    float* out = (float*)d_out;

    int M = in_sizes[0] / D;   // 100000
    int E = in_sizes[1];       // 1600000

    cudaFuncSetAttribute(k_gemm, cudaFuncAttributeMaxDynamicSharedMemorySize,
                         GM_SMEM_BYTES);

    k_transpose<<<(D * D + 255) / 256, 256>>>(W);
    k_zero<<<1024, 256>>>((float4*)out, out_size / 4);
    k_scatter<<<(E + 255) / 256, 256>>>(h, esrc, edst, out, E);
    k_gemm<<<(M + GM_BM - 1) / GM_BM, 256, GM_SMEM_BYTES>>>(out, b, out, M);
}